// round 15
// baseline (speedup 1.0000x reference)
#include <cuda_runtime.h>
#include <cuda_fp16.h>
#include <math.h>

#define N_NODE 100000
#define EMB 112
#define NNZ 1600000
#define BATCH 512
#define SEQ 50
#define NR (BATCH*SEQ)
#define NBLK 98     // ceil(100000/1024)
#define CONVBLK 512 // extra scan1 blocks doing fp16 conversion

// ---------------- device scratch ----------------
__device__ __align__(16) float g_item[N_NODE*EMB];
__device__ __align__(16) __half g_embh[N_NODE*128];   // fp16 emb0 table, 256B rows (pad stays 0)
__device__ __align__(16) __half g_emb1h[N_NODE*128];  // fp16 emb1 table (pad stays 0)
__device__ int    g_count[N_NODE];          // zero-init; re-zeroed by k_scatter each call
__device__ int    g_rowstart[N_NODE];       // block-local exclusive scan
__device__ int    g_pos[NNZ];
__device__ __align__(8) float2 g_edge[NNZ]; // {val, bitcast(col)}
__device__ int    g_bsums[NBLK];
__device__ int    g_boff[NBLK];             // global block offsets (computed once in scan1)
__device__ int    g_done;                   // zero-init; reset by scan1's last block
__device__ unsigned char g_needed[N_NODE];  // zero-init; re-zeroed by spmm layer-2
__device__ __align__(16) float g_Q[NR*EMB];
__device__ __align__(16) float g_K[NR*EMB];
__device__ int    g_rowlist[NR];
__device__ int    g_nvalid;                 // zero-init; re-zeroed by k_final
__device__ __align__(16) float g_acc[BATCH*EMB];
__device__ __align__(16) float g_t1[BATCH*EMB];
__device__ __align__(16) float g_t2[BATCH*EMB];
__device__ __align__(16) float g_s1[BATCH*EMB];
__device__ __align__(16) float g_s2[BATCH*EMB];

// ---------------- hist: per-edge rank + count + session prep ----------------
__global__ void k_hist(const int* __restrict__ rows, const int* __restrict__ sitem,
                       const int* __restrict__ slen) {
    int i = blockIdx.x*blockDim.x + threadIdx.x;
    if (i < NNZ) {
        int r = rows[i];
        g_pos[i] = atomicAdd(&g_count[r], 1);
    }
    if (i < NR) {
        int it = sitem[i];
        if (it > 0) g_needed[it-1] = 1;
    }
    if (i < BATCH) {
        int len = slen[i];
        if (len < 1) len = 1;
        if (len > SEQ) len = SEQ;
        int base = atomicAdd(&g_nvalid, len);
        for (int l = 0; l < len; l++) g_rowlist[base + l] = i*SEQ + l;
    }
}

// ---------------- scan1: block-local scan; last scan-block publishes g_boff;
//                  extra blocks convert emb->fp16 ----------------
__global__ void k_scan1(const float4* __restrict__ emb) {
    if (blockIdx.x >= NBLK) {
        int idx = (blockIdx.x - NBLK)*blockDim.x + threadIdx.x;
        const int total = N_NODE*28;
        const int stride = CONVBLK*1024;
        for (int j = idx; j < total; j += stride) {
            int row = j / 28;
            int q   = j - row*28;
            float4 v = emb[j];
            __half2 h0 = __floats2half2_rn(v.x, v.y);
            __half2 h1 = __floats2half2_rn(v.z, v.w);
            ((uint2*)g_embh)[row*32 + q] =
                make_uint2(*(unsigned int*)&h0, *(unsigned int*)&h1);
        }
        return;
    }
    __shared__ int wsum[32];
    __shared__ int donef;
    int tid = threadIdx.x;
    int lane = tid & 31, wid = tid >> 5;
    int idx = blockIdx.x*1024 + tid;
    int v = (idx < N_NODE) ? g_count[idx] : 0;
    int x = v;
    #pragma unroll
    for (int o = 1; o < 32; o <<= 1) {
        int t = __shfl_up_sync(0xffffffffu, x, o);
        if (lane >= o) x += t;
    }
    if (lane == 31) wsum[wid] = x;
    __syncthreads();
    if (tid < 32) {
        int w = wsum[tid];
        #pragma unroll
        for (int o = 1; o < 32; o <<= 1) {
            int t = __shfl_up_sync(0xffffffffu, w, o);
            if (tid >= o) w += t;
        }
        wsum[tid] = w;
    }
    __syncthreads();
    int pre = (wid > 0) ? wsum[wid-1] : 0;
    if (idx < N_NODE) g_rowstart[idx] = pre + x - v;   // block-local exclusive
    if (tid == 0) g_bsums[blockIdx.x] = wsum[31];

    if (tid == 0) {
        __threadfence();
        int t = atomicAdd(&g_done, 1);
        donef = (t == NBLK-1);
    }
    __syncthreads();
    if (donef) {
        int bv = 0, bx = 0;
        if (tid < 128) {
            bv = (tid < NBLK) ? g_bsums[tid] : 0;
            bx = bv;
            #pragma unroll
            for (int o = 1; o < 32; o <<= 1) {
                int t = __shfl_up_sync(0xffffffffu, bx, o);
                if (lane >= o) bx += t;
            }
            if (lane == 31) wsum[tid >> 5] = bx;
        }
        __syncthreads();
        if (tid == 0) {
            int r = 0;
            #pragma unroll
            for (int i = 0; i < 4; i++) { int t = wsum[i]; wsum[i] = r; r += t; }
            g_done = 0;   // restore invariant
        }
        __syncthreads();
        if (tid < NBLK) g_boff[tid] = bx - bv + wsum[tid >> 5];
    }
}

// ---------------- scatter; re-zero g_count ----------------
__global__ void k_scatter(const int* __restrict__ rows, const int* __restrict__ cols,
                          const float* __restrict__ vals) {
    __shared__ int sh_off[NBLK];
    int tid = threadIdx.x;
    if (tid < NBLK) sh_off[tid] = g_boff[tid];
    __syncthreads();
    int i = blockIdx.x*512 + tid;
    if (i < NNZ) {
        int r = rows[i];
        int dest = g_rowstart[r] + sh_off[r >> 10] + g_pos[i];
        g_edge[dest] = make_float2(vals[i], __int_as_float(cols[i]));
    }
    if (i < N_NODE) g_count[i] = 0;  // restore invariant for next call
}

__device__ __forceinline__ void fma_h(float4& acc, float v, uint2 x) {
    float2 f0 = __half22float2(*(__half2*)&x.x);
    float2 f1 = __half22float2(*(__half2*)&x.y);
    acc.x = fmaf(v, f0.x, acc.x);
    acc.y = fmaf(v, f0.y, acc.y);
    acc.z = fmaf(v, f1.x, acc.z);
    acc.w = fmaf(v, f1.y, acc.w);
}

__device__ __forceinline__ float4 h_to_f4(uint2 x) {
    float2 f0 = __half22float2(*(__half2*)&x.x);
    float2 f1 = __half22float2(*(__half2*)&x.y);
    return make_float4(f0.x, f0.y, f1.x, f1.y);
}

// 4-deep MLP inner loop; gathers predicate-free (lanes 28-31 read the zero pad)
__device__ __forceinline__ float4 spmm_row(const uint2* __restrict__ tbl,
                                           int s, int e, int lane) {
    float4 acc = make_float4(0.f, 0.f, 0.f, 0.f);
    int j = s;
    for (; j + 4 <= e; j += 4) {
        float2 e0 = g_edge[j],   e1 = g_edge[j+1];
        float2 e2 = g_edge[j+2], e3 = g_edge[j+3];
        uint2 x0 = tbl[__float_as_int(e0.y)*32 + lane];
        uint2 x1 = tbl[__float_as_int(e1.y)*32 + lane];
        uint2 x2 = tbl[__float_as_int(e2.y)*32 + lane];
        uint2 x3 = tbl[__float_as_int(e3.y)*32 + lane];
        fma_h(acc, e0.x, x0);
        fma_h(acc, e1.x, x1);
        fma_h(acc, e2.x, x2);
        fma_h(acc, e3.x, x3);
    }
    for (; j < e; j++) {
        float2 ev = g_edge[j];
        fma_h(acc, ev.x, tbl[__float_as_int(ev.y)*32 + lane]);
    }
    return acc;
}

// row extent from block-local scan + published block offsets (L1-hot, no smem/sync)
__device__ __forceinline__ void row_extent(int w, int& s, int& e) {
    s = g_rowstart[w] + g_boff[w >> 10];
    e = (w == N_NODE-1) ? NNZ : (g_rowstart[w+1] + g_boff[(w+1) >> 10]);
}

// ---------------- SpMM layer-0: 64-thread blocks (2 rows); writes ONLY fp16 emb1 table ----------------
__global__ void k_spmm_h() {
    int w = blockIdx.x*2 + (threadIdx.x >> 5);
    if (w >= N_NODE) return;
    int lane = threadIdx.x & 31;
    int s, e;
    row_extent(w, s, e);
    float4 acc = spmm_row((const uint2*)g_embh, s, e, lane);
    if (lane < 28) {
        __half2 h0 = __floats2half2_rn(acc.x, acc.y);
        __half2 h1 = __floats2half2_rn(acc.z, acc.w);
        ((uint2*)g_emb1h)[w*32 + lane] =
            make_uint2(*(unsigned int*)&h0, *(unsigned int*)&h1);
    }
}

// ---------------- SpMM layer-2 (filtered): item = (emb0h+emb1h+sum)/3 ----------------
__global__ void k_spmm2(float4* __restrict__ out) {
    int w = blockIdx.x*2 + (threadIdx.x >> 5);
    if (w >= N_NODE) return;
    if (!g_needed[w]) return;
    int lane = threadIdx.x & 31;
    int s, e;
    row_extent(w, s, e);
    float4 acc = spmm_row((const uint2*)g_emb1h, s, e, lane);
    if (lane < 28) {
        float4 a = h_to_f4(((const uint2*)g_embh)[w*32 + lane]);
        float4 b = h_to_f4(((const uint2*)g_emb1h)[w*32 + lane]);
        const float third = 1.f/3.f;
        acc.x = (a.x + b.x + acc.x)*third;
        acc.y = (a.y + b.y + acc.y)*third;
        acc.z = (a.z + b.z + acc.z)*third;
        acc.w = (a.w + b.w + acc.w)*third;
        out[w*28 + lane] = acc;
    }
    if (lane == 0) g_needed[w] = 0;  // restore invariant
}

// ---------------- fused Q/K GEMM on valid rows ----------------
__global__ void k_qk(const float* __restrict__ Wq, const float* __restrict__ Wk,
                     const int* __restrict__ sitem) {
    __shared__ float Bs[28*224];
    __shared__ float As[64*28];
    __shared__ int   rows_sh[64];
    __shared__ int   items_sh[64];
    int count = g_nvalid;
    int start = blockIdx.x * 64;
    if (start >= count) return;
    int tid = threadIdx.x;
    int tx = tid & 15, ty = tid >> 4;
    if (tid < 64) {
        int r = (start + tid < count) ? g_rowlist[start + tid] : -1;
        rows_sh[tid] = r;
        items_sh[tid] = (r >= 0) ? (sitem[r] - 1) : -1;
    }
    float acc[4][14];
    #pragma unroll
    for (int i = 0; i < 4; i++)
        #pragma unroll
        for (int j = 0; j < 14; j++) acc[i][j] = 0.f;

    for (int k0 = 0; k0 < 112; k0 += 28) {
        __syncthreads();
        for (int idx = tid; idx < 28*224; idx += 256) {
            int kk = idx / 224, e = idx - kk*224;
            Bs[idx] = (e < 112) ? Wq[(k0+kk)*112 + e] : Wk[(k0+kk)*112 + (e-112)];
        }
        for (int idx = tid; idx < 64*28; idx += 256) {
            int i = idx / 28, kk = idx - i*28;
            int it = items_sh[i];
            As[idx] = (it >= 0) ? g_item[it*112 + k0 + kk] : 0.f;
        }
        __syncthreads();
        #pragma unroll
        for (int kk = 0; kk < 28; kk++) {
            float a[4], b[14];
            #pragma unroll
            for (int i = 0; i < 4; i++) a[i] = As[(ty + 16*i)*28 + kk];
            #pragma unroll
            for (int j = 0; j < 14; j++) b[j] = Bs[kk*224 + tx + 16*j];
            #pragma unroll
            for (int i = 0; i < 4; i++)
                #pragma unroll
                for (int j = 0; j < 14; j++) acc[i][j] = fmaf(a[i], b[j], acc[i][j]);
        }
    }
    #pragma unroll
    for (int i = 0; i < 4; i++) {
        int li = ty + 16*i;
        int r = rows_sh[li];
        if (r < 0) continue;
        #pragma unroll
        for (int j = 0; j < 14; j++) {
            int e = tx + 16*j;
            float v = 1.f / (1.f + __expf(-acc[i][j]));
            if (e < 112) g_Q[r*112 + e] = v;
            else         g_K[r*112 + (e-112)] = v;
        }
    }
}

// ---------------- attention + fused layer-0 linear ----------------
__global__ void k_attn(const int* __restrict__ slen, const int* __restrict__ sitem,
                       const float* __restrict__ W0) {
    __shared__ float Qs[SEQ*112];
    __shared__ __align__(8) float Kt[112*50];
    __shared__ float alphas[64];
    __shared__ float betas[64];
    __shared__ __align__(16) float xs[112];
    __shared__ int   its[SEQ];
    int b = blockIdx.x;
    int tid = threadIdx.x;
    int len = slen[b];
    if (len < 1) len = 1;
    if (len > SEQ) len = SEQ;

    if (tid < len) its[tid] = sitem[b*SEQ + tid] - 1;
    for (int idx = tid; idx < len*112; idx += 128) {
        int l = idx / 112, k = idx - l*112;
        Qs[l*112 + k] = g_Q[(b*SEQ + l)*112 + k];
        Kt[k*50 + l]  = g_K[(b*SEQ + l)*112 + k];
    }
    if (tid < 64) alphas[tid] = -1e30f;
    __syncthreads();

    int wid = tid >> 5, lane = tid & 31;
    const float isq = 0.09449111825230679f;  // 1/sqrt(112)
    for (int g = wid; 2*g < len; g += 4) {
        int l0 = 2*g, l1 = 2*g + 1;
        bool has1 = l1 < len;
        float d00 = 0.f, d01 = 0.f, d10 = 0.f, d11 = 0.f;
        int m0 = 2*lane, m1 = m0 + 1;
        if (lane < 25) {
            for (int k = 0; k < 112; k++) {
                float q0 = Qs[l0*112 + k];
                float2 kv = *(const float2*)&Kt[k*50 + m0];
                d00 = fmaf(q0, kv.x, d00);
                d01 = fmaf(q0, kv.y, d01);
                if (has1) {
                    float q1 = Qs[l1*112 + k];
                    d10 = fmaf(q1, kv.x, d10);
                    d11 = fmaf(q1, kv.y, d11);
                }
            }
        }
        float s0 = 0.f, s1 = 0.f;
        if (m0 < len && m0 != l0) s0 += isq / (1.f + __expf(-d00));
        if (m1 < len && m1 != l0) s0 += isq / (1.f + __expf(-d01));
        if (has1) {
            if (m0 < len && m0 != l1) s1 += isq / (1.f + __expf(-d10));
            if (m1 < len && m1 != l1) s1 += isq / (1.f + __expf(-d11));
        }
        #pragma unroll
        for (int o = 16; o; o >>= 1) {
            s0 += __shfl_down_sync(0xffffffffu, s0, o);
            s1 += __shfl_down_sync(0xffffffffu, s1, o);
        }
        if (lane == 0) {
            alphas[l0] = s0 / (float)len;
            if (has1) alphas[l1] = s1 / (float)len;
        }
    }
    __syncthreads();
    if (wid == 0) {
        float a1 = alphas[lane];
        float a2 = alphas[lane + 32];
        float mx = fmaxf(a1, a2);
        #pragma unroll
        for (int o = 16; o; o >>= 1) mx = fmaxf(mx, __shfl_xor_sync(0xffffffffu, mx, o));
        float e1 = __expf(a1 - mx), e2 = __expf(a2 - mx);
        float s = e1 + e2;
        #pragma unroll
        for (int o = 16; o; o >>= 1) s += __shfl_xor_sync(0xffffffffu, s, o);
        float inv = 1.f / s;
        betas[lane] = e1 * inv;
        betas[lane + 32] = e2 * inv;
    }
    __syncthreads();
    if (tid < 112) {
        float acc = 0.f;
        for (int l = 0; l < len; l++)
            acc = fmaf(betas[l], g_item[its[l]*112 + tid], acc);
        g_acc[b*112 + tid] = acc;
        xs[tid] = acc;
        g_t2[b*112 + tid] = 0.f;   // zero split-K targets for layer 0
        g_s1[b*112 + tid] = 0.f;
    }
    __syncthreads();
    if (tid < 112) {
        const float4* w4 = (const float4*)(W0 + tid*112);
        const float4* x4 = (const float4*)xs;
        float acc = 0.f;
        #pragma unroll 7
        for (int d = 0; d < 28; d++) {
            float4 w = w4[d], xv = x4[d];
            acc = fmaf(w.x, xv.x, acc);
            acc = fmaf(w.y, xv.y, acc);
            acc = fmaf(w.z, xv.z, acc);
            acc = fmaf(w.w, xv.w, acc);
        }
        g_t1[b*112 + tid] = acc;
    }
}

// ---------------- Linear out = in @ W^T; fused zeroing; normalize-accumulate ----------------
__global__ void k_lin(const float* __restrict__ in, const float* __restrict__ W,
                      float* __restrict__ out, float* __restrict__ z1,
                      float* __restrict__ z2, int donorm) {
    __shared__ __align__(16) float xs[112];
    __shared__ float red[4];
    int b = blockIdx.x, tid = threadIdx.x;
    float x = 0.f;
    if (tid < 112) {
        x = in[b*112 + tid];
        xs[tid] = x;
        z1[b*112 + tid] = 0.f;
        z2[b*112 + tid] = 0.f;
    }
    __syncthreads();
    if (donorm) {
        float ss = x*x;
        #pragma unroll
        for (int o = 16; o; o >>= 1) ss += __shfl_xor_sync(0xffffffffu, ss, o);
        if ((tid & 31) == 0) red[tid >> 5] = ss;
        __syncthreads();
        float tot = red[0] + red[1] + red[2] + red[3];
        float inv = 1.f / fmaxf(sqrtf(tot), 1e-12f);
        if (tid < 112) g_acc[b*112 + tid] += x * inv;
    }
    if (tid < 112) {
        const float4* w4 = (const float4*)(W + tid*112);
        const float4* x4 = (const float4*)xs;
        float acc = 0.f;
        #pragma unroll 7
        for (int d = 0; d < 28; d++) {
            float4 w = w4[d], xv = x4[d];
            acc = fmaf(w.x, xv.x, acc);
            acc = fmaf(w.y, xv.y, acc);
            acc = fmaf(w.z, xv.z, acc);
            acc = fmaf(w.w, xv.w, acc);
        }
        out[b*112 + tid] = acc;
    }
}

// ---------------- split-K GEMM: out += Amat[512,512] @ X[512,112] (atomic) ----------------
__global__ void k_gemm(const float* __restrict__ Amat, const float* __restrict__ X,
                       float* __restrict__ out) {
    __shared__ float As[64*17];
    __shared__ float Bs[16*112];
    int mt = blockIdx.x, ks = blockIdx.y;
    int row0 = mt*64, kbase = ks*64;
    int tid = threadIdx.x;
    int tx = tid & 15, ty = tid >> 4;
    float acc[4][7];
    #pragma unroll
    for (int i = 0; i < 4; i++)
        #pragma unroll
        for (int j = 0; j < 7; j++) acc[i][j] = 0.f;

    for (int kc = 0; kc < 64; kc += 16) {
        __syncthreads();
        for (int idx = tid; idx < 64*16; idx += 256) {
            int i = idx >> 4, kk = idx & 15;
            As[i*17 + kk] = Amat[(row0 + i)*512 + kbase + kc + kk];
        }
        for (int idx = tid; idx < 16*112; idx += 256) {
            int kk = idx / 112, e = idx - kk*112;
            Bs[kk*112 + e] = X[(kbase + kc + kk)*112 + e];
        }
        __syncthreads();
        #pragma unroll
        for (int kk = 0; kk < 16; kk++) {
            float a[4], bb[7];
            #pragma unroll
            for (int i = 0; i < 4; i++) a[i] = As[(ty + 16*i)*17 + kk];
            #pragma unroll
            for (int j = 0; j < 7; j++) bb[j] = Bs[kk*112 + tx + 16*j];
            #pragma unroll
            for (int i = 0; i < 4; i++)
                #pragma unroll
                for (int j = 0; j < 7; j++) acc[i][j] = fmaf(a[i], bb[j], acc[i][j]);
        }
    }
    #pragma unroll
    for (int i = 0; i < 4; i++)
        #pragma unroll
        for (int j = 0; j < 7; j++)
            atomicAdd(&out[(row0 + ty + 16*i)*112 + tx + 16*j], acc[i][j]);
}

// ---------------- final: acc2 = (g_acc + s2/||s2||) / 3 -> d_out; restore g_nvalid ----------------
__global__ void k_final(const float* __restrict__ cur, float* __restrict__ dout) {
    if (blockIdx.x == 0 && threadIdx.x == 0) g_nvalid = 0;
    int w = (blockIdx.x*blockDim.x + threadIdx.x) >> 5;
    if (w >= BATCH) return;
    int lane = threadIdx.x & 31;
    float4 v = make_float4(0.f, 0.f, 0.f, 0.f);
    float ss = 0.f;
    if (lane < 28) {
        v = ((const float4*)cur)[w*28 + lane];
        ss = v.x*v.x + v.y*v.y + v.z*v.z + v.w*v.w;
    }
    #pragma unroll
    for (int o = 16; o; o >>= 1) ss += __shfl_xor_sync(0xffffffffu, ss, o);
    float inv = 1.f / fmaxf(sqrtf(ss), 1e-12f);
    if (lane < 28) {
        float4 a = ((const float4*)g_acc)[w*28 + lane];
        const float third = 1.f/3.f;
        a.x = fmaf(v.x, inv, a.x) * third;
        a.y = fmaf(v.y, inv, a.y) * third;
        a.z = fmaf(v.z, inv, a.z) * third;
        a.w = fmaf(v.w, inv, a.w) * third;
        ((float4*)dout)[w*28 + lane] = a;
    }
}

// ---------------- host launcher ----------------
extern "C" void kernel_launch(void* const* d_in, const int* in_sizes, int n_in,
                              void* d_out, int out_size) {
    (void)in_sizes; (void)n_in; (void)out_size;
    const float* emb      = (const float*)d_in[0];
    const float* adj_vals = (const float*)d_in[1];
    const float* Wq       = (const float*)d_in[2];
    const float* Wk       = (const float*)d_in[3];
    const float* Wsess    = (const float*)d_in[4];
    const float* D        = (const float*)d_in[5];
    const float* A        = (const float*)d_in[6];
    const int*   rows     = (const int*)d_in[7];
    const int*   cols     = (const int*)d_in[8];
    const int*   sitem    = (const int*)d_in[9];
    const int*   slen     = (const int*)d_in[10];
    float*       out      = (float*)d_out;

    float *p_item, *p_t1, *p_t2, *p_s1, *p_s2;
    cudaGetSymbolAddress((void**)&p_item, g_item);
    cudaGetSymbolAddress((void**)&p_t1, g_t1);
    cudaGetSymbolAddress((void**)&p_t2, g_t2);
    cudaGetSymbolAddress((void**)&p_s1, g_s1);
    cudaGetSymbolAddress((void**)&p_s2, g_s2);

    // CSR build; fp16 conversion rides on scan1's idle SMs
    k_hist<<<(NNZ + 255)/256, 256>>>(rows, sitem, slen);
    k_scan1<<<NBLK + CONVBLK, 1024>>>((const float4*)emb);
    k_scatter<<<NNZ/512, 512>>>(rows, cols, adj_vals);

    // HyperConv layers: 64-thread blocks (2 rows), all-fp16 tables
    k_spmm_h<<<(N_NODE + 1)/2, 64>>>();
    k_spmm2<<<(N_NODE + 1)/2, 64>>>((float4*)p_item);

    // Q/K + attention pooling (layer-0 linear fused into attn)
    k_qk<<<NR/64, 256>>>(Wq, Wk, sitem);
    k_attn<<<BATCH, 128>>>(slen, sitem, Wsess);

    // SessConv layer 0 (linear already done in attn)
    k_gemm<<<dim3(8, 8), 256>>>(A, p_t1, p_t2);
    k_gemm<<<dim3(8, 8), 256>>>(D, p_t2, p_s1);

    // SessConv layer 1 (fused normalize(s1)->acc)
    k_lin<<<BATCH, 128>>>(p_s1, Wsess + 112*112, p_t1, p_t2, p_s2, 1);
    k_gemm<<<dim3(8, 8), 256>>>(A, p_t1, p_t2);
    k_gemm<<<dim3(8, 8), 256>>>(D, p_t2, p_s2);

    k_final<<<(BATCH*32 + 255)/256, 256>>>(p_s2, out);
}

// round 16
// speedup vs baseline: 1.0318x; 1.0318x over previous
#include <cuda_runtime.h>
#include <cuda_fp16.h>
#include <math.h>

#define N_NODE 100000
#define EMB 112
#define NNZ 1600000
#define BATCH 512
#define SEQ 50
#define NR (BATCH*SEQ)
#define NBLK 98     // ceil(100000/1024)
#define CONVBLK 512 // extra scan1 blocks doing fp16 conversion

// ---------------- device scratch ----------------
__device__ __align__(16) float g_item[N_NODE*EMB];
__device__ __align__(16) __half g_embh[N_NODE*128];   // fp16 emb0 table, 256B rows (pad stays 0)
__device__ __align__(16) __half g_emb1h[N_NODE*128];  // fp16 emb1 table (pad stays 0)
__device__ int    g_count[N_NODE];          // zero-init; re-zeroed by k_scatter each call
__device__ int    g_rowstart[N_NODE];       // block-local exclusive scan
__device__ int    g_pos[NNZ];
__device__ __align__(8) float2 g_edge[NNZ]; // {val, bitcast(col)}
__device__ int    g_bsums[NBLK];
__device__ int    g_boff[NBLK];             // global block offsets (computed once in scan1)
__device__ int    g_done;                   // zero-init; reset by scan1's last block
__device__ unsigned char g_needed[N_NODE];  // zero-init; re-zeroed by spmm layer-2
__device__ __align__(16) float g_Q[NR*EMB];
__device__ __align__(16) float g_K[NR*EMB];
__device__ int    g_rowlist[NR];
__device__ int    g_nvalid;                 // zero-init; re-zeroed by k_final
__device__ __align__(16) float g_acc[BATCH*EMB];
__device__ __align__(16) float g_t1[BATCH*EMB];
__device__ __align__(16) float g_t2[BATCH*EMB];
__device__ __align__(16) float g_s1[BATCH*EMB];
__device__ __align__(16) float g_s2[BATCH*EMB];

// ---------------- hist: per-edge rank + count + session prep ----------------
__global__ void k_hist(const int* __restrict__ rows, const int* __restrict__ sitem,
                       const int* __restrict__ slen) {
    int i = blockIdx.x*blockDim.x + threadIdx.x;
    if (i < NNZ) {
        int r = rows[i];
        g_pos[i] = atomicAdd(&g_count[r], 1);
    }
    if (i < NR) {
        int it = sitem[i];
        if (it > 0) g_needed[it-1] = 1;
    }
    if (i < BATCH) {
        int len = slen[i];
        if (len < 1) len = 1;
        if (len > SEQ) len = SEQ;
        int base = atomicAdd(&g_nvalid, len);
        for (int l = 0; l < len; l++) g_rowlist[base + l] = i*SEQ + l;
    }
}

// ---------------- scan1: block-local scan; last scan-block publishes g_boff;
//                  extra blocks convert emb->fp16 ----------------
__global__ void k_scan1(const float4* __restrict__ emb) {
    if (blockIdx.x >= NBLK) {
        int idx = (blockIdx.x - NBLK)*blockDim.x + threadIdx.x;
        const int total = N_NODE*28;
        const int stride = CONVBLK*1024;
        for (int j = idx; j < total; j += stride) {
            int row = j / 28;
            int q   = j - row*28;
            float4 v = emb[j];
            __half2 h0 = __floats2half2_rn(v.x, v.y);
            __half2 h1 = __floats2half2_rn(v.z, v.w);
            ((uint2*)g_embh)[row*32 + q] =
                make_uint2(*(unsigned int*)&h0, *(unsigned int*)&h1);
        }
        return;
    }
    __shared__ int wsum[32];
    __shared__ int donef;
    int tid = threadIdx.x;
    int lane = tid & 31, wid = tid >> 5;
    int idx = blockIdx.x*1024 + tid;
    int v = (idx < N_NODE) ? g_count[idx] : 0;
    int x = v;
    #pragma unroll
    for (int o = 1; o < 32; o <<= 1) {
        int t = __shfl_up_sync(0xffffffffu, x, o);
        if (lane >= o) x += t;
    }
    if (lane == 31) wsum[wid] = x;
    __syncthreads();
    if (tid < 32) {
        int w = wsum[tid];
        #pragma unroll
        for (int o = 1; o < 32; o <<= 1) {
            int t = __shfl_up_sync(0xffffffffu, w, o);
            if (tid >= o) w += t;
        }
        wsum[tid] = w;
    }
    __syncthreads();
    int pre = (wid > 0) ? wsum[wid-1] : 0;
    if (idx < N_NODE) g_rowstart[idx] = pre + x - v;   // block-local exclusive
    if (tid == 0) g_bsums[blockIdx.x] = wsum[31];

    if (tid == 0) {
        __threadfence();
        int t = atomicAdd(&g_done, 1);
        donef = (t == NBLK-1);
    }
    __syncthreads();
    if (donef) {
        int bv = 0, bx = 0;
        if (tid < 128) {
            bv = (tid < NBLK) ? g_bsums[tid] : 0;
            bx = bv;
            #pragma unroll
            for (int o = 1; o < 32; o <<= 1) {
                int t = __shfl_up_sync(0xffffffffu, bx, o);
                if (lane >= o) bx += t;
            }
            if (lane == 31) wsum[tid >> 5] = bx;
        }
        __syncthreads();
        if (tid == 0) {
            int r = 0;
            #pragma unroll
            for (int i = 0; i < 4; i++) { int t = wsum[i]; wsum[i] = r; r += t; }
            g_done = 0;   // restore invariant
        }
        __syncthreads();
        if (tid < NBLK) g_boff[tid] = bx - bv + wsum[tid >> 5];
    }
}

// ---------------- scatter; re-zero g_count ----------------
__global__ void k_scatter(const int* __restrict__ rows, const int* __restrict__ cols,
                          const float* __restrict__ vals) {
    __shared__ int sh_off[NBLK];
    int tid = threadIdx.x;
    if (tid < NBLK) sh_off[tid] = g_boff[tid];
    __syncthreads();
    int i = blockIdx.x*512 + tid;
    if (i < NNZ) {
        int r = rows[i];
        int dest = g_rowstart[r] + sh_off[r >> 10] + g_pos[i];
        g_edge[dest] = make_float2(vals[i], __int_as_float(cols[i]));
    }
    if (i < N_NODE) g_count[i] = 0;  // restore invariant for next call
}

__device__ __forceinline__ void fma_h(float4& acc, float v, uint2 x) {
    float2 f0 = __half22float2(*(__half2*)&x.x);
    float2 f1 = __half22float2(*(__half2*)&x.y);
    acc.x = fmaf(v, f0.x, acc.x);
    acc.y = fmaf(v, f0.y, acc.y);
    acc.z = fmaf(v, f1.x, acc.z);
    acc.w = fmaf(v, f1.y, acc.w);
}

__device__ __forceinline__ float4 h_to_f4(uint2 x) {
    float2 f0 = __half22float2(*(__half2*)&x.x);
    float2 f1 = __half22float2(*(__half2*)&x.y);
    return make_float4(f0.x, f0.y, f1.x, f1.y);
}

// 4-deep MLP inner loop; gathers predicate-free (lanes 28-31 read the zero pad)
__device__ __forceinline__ float4 spmm_row(const uint2* __restrict__ tbl,
                                           int s, int e, int lane) {
    float4 acc = make_float4(0.f, 0.f, 0.f, 0.f);
    int j = s;
    for (; j + 4 <= e; j += 4) {
        float2 e0 = g_edge[j],   e1 = g_edge[j+1];
        float2 e2 = g_edge[j+2], e3 = g_edge[j+3];
        uint2 x0 = tbl[__float_as_int(e0.y)*32 + lane];
        uint2 x1 = tbl[__float_as_int(e1.y)*32 + lane];
        uint2 x2 = tbl[__float_as_int(e2.y)*32 + lane];
        uint2 x3 = tbl[__float_as_int(e3.y)*32 + lane];
        fma_h(acc, e0.x, x0);
        fma_h(acc, e1.x, x1);
        fma_h(acc, e2.x, x2);
        fma_h(acc, e3.x, x3);
    }
    for (; j < e; j++) {
        float2 ev = g_edge[j];
        fma_h(acc, ev.x, tbl[__float_as_int(ev.y)*32 + lane]);
    }
    return acc;
}

// row extent from block-local scan + published block offsets (L1-hot, no smem/sync)
__device__ __forceinline__ void row_extent(int w, int& s, int& e) {
    s = g_rowstart[w] + g_boff[w >> 10];
    e = (w == N_NODE-1) ? NNZ : (g_rowstart[w+1] + g_boff[(w+1) >> 10]);
}

// ---------------- SpMM layer-0: 128-thread blocks (4 rows); writes ONLY fp16 emb1 table ----------------
__global__ void k_spmm_h() {
    int w = blockIdx.x*4 + (threadIdx.x >> 5);
    if (w >= N_NODE) return;
    int lane = threadIdx.x & 31;
    int s, e;
    row_extent(w, s, e);
    float4 acc = spmm_row((const uint2*)g_embh, s, e, lane);
    if (lane < 28) {
        __half2 h0 = __floats2half2_rn(acc.x, acc.y);
        __half2 h1 = __floats2half2_rn(acc.z, acc.w);
        ((uint2*)g_emb1h)[w*32 + lane] =
            make_uint2(*(unsigned int*)&h0, *(unsigned int*)&h1);
    }
}

// ---------------- SpMM layer-2 (filtered): item = (emb0h+emb1h+sum)/3 ----------------
__global__ void k_spmm2(float4* __restrict__ out) {
    int w = blockIdx.x*4 + (threadIdx.x >> 5);
    if (w >= N_NODE) return;
    if (!g_needed[w]) return;
    int lane = threadIdx.x & 31;
    int s, e;
    row_extent(w, s, e);
    float4 acc = spmm_row((const uint2*)g_emb1h, s, e, lane);
    if (lane < 28) {
        float4 a = h_to_f4(((const uint2*)g_embh)[w*32 + lane]);
        float4 b = h_to_f4(((const uint2*)g_emb1h)[w*32 + lane]);
        const float third = 1.f/3.f;
        acc.x = (a.x + b.x + acc.x)*third;
        acc.y = (a.y + b.y + acc.y)*third;
        acc.z = (a.z + b.z + acc.z)*third;
        acc.w = (a.w + b.w + acc.w)*third;
        out[w*28 + lane] = acc;
    }
    if (lane == 0) g_needed[w] = 0;  // restore invariant
}

// ---------------- fused Q/K GEMM on valid rows ----------------
__global__ void k_qk(const float* __restrict__ Wq, const float* __restrict__ Wk,
                     const int* __restrict__ sitem) {
    __shared__ float Bs[28*224];
    __shared__ float As[64*28];
    __shared__ int   rows_sh[64];
    __shared__ int   items_sh[64];
    int count = g_nvalid;
    int start = blockIdx.x * 64;
    if (start >= count) return;
    int tid = threadIdx.x;
    int tx = tid & 15, ty = tid >> 4;
    if (tid < 64) {
        int r = (start + tid < count) ? g_rowlist[start + tid] : -1;
        rows_sh[tid] = r;
        items_sh[tid] = (r >= 0) ? (sitem[r] - 1) : -1;
    }
    float acc[4][14];
    #pragma unroll
    for (int i = 0; i < 4; i++)
        #pragma unroll
        for (int j = 0; j < 14; j++) acc[i][j] = 0.f;

    for (int k0 = 0; k0 < 112; k0 += 28) {
        __syncthreads();
        for (int idx = tid; idx < 28*224; idx += 256) {
            int kk = idx / 224, e = idx - kk*224;
            Bs[idx] = (e < 112) ? Wq[(k0+kk)*112 + e] : Wk[(k0+kk)*112 + (e-112)];
        }
        for (int idx = tid; idx < 64*28; idx += 256) {
            int i = idx / 28, kk = idx - i*28;
            int it = items_sh[i];
            As[idx] = (it >= 0) ? g_item[it*112 + k0 + kk] : 0.f;
        }
        __syncthreads();
        #pragma unroll
        for (int kk = 0; kk < 28; kk++) {
            float a[4], b[14];
            #pragma unroll
            for (int i = 0; i < 4; i++) a[i] = As[(ty + 16*i)*28 + kk];
            #pragma unroll
            for (int j = 0; j < 14; j++) b[j] = Bs[kk*224 + tx + 16*j];
            #pragma unroll
            for (int i = 0; i < 4; i++)
                #pragma unroll
                for (int j = 0; j < 14; j++) acc[i][j] = fmaf(a[i], b[j], acc[i][j]);
        }
    }
    #pragma unroll
    for (int i = 0; i < 4; i++) {
        int li = ty + 16*i;
        int r = rows_sh[li];
        if (r < 0) continue;
        #pragma unroll
        for (int j = 0; j < 14; j++) {
            int e = tx + 16*j;
            float v = 1.f / (1.f + __expf(-acc[i][j]));
            if (e < 112) g_Q[r*112 + e] = v;
            else         g_K[r*112 + (e-112)] = v;
        }
    }
}

// ---------------- attention + fused layer-0 linear ----------------
__global__ void k_attn(const int* __restrict__ slen, const int* __restrict__ sitem,
                       const float* __restrict__ W0) {
    __shared__ float Qs[SEQ*112];
    __shared__ __align__(8) float Kt[112*50];
    __shared__ float alphas[64];
    __shared__ float betas[64];
    __shared__ __align__(16) float xs[112];
    __shared__ int   its[SEQ];
    int b = blockIdx.x;
    int tid = threadIdx.x;
    int len = slen[b];
    if (len < 1) len = 1;
    if (len > SEQ) len = SEQ;

    if (tid < len) its[tid] = sitem[b*SEQ + tid] - 1;
    for (int idx = tid; idx < len*112; idx += 128) {
        int l = idx / 112, k = idx - l*112;
        Qs[l*112 + k] = g_Q[(b*SEQ + l)*112 + k];
        Kt[k*50 + l]  = g_K[(b*SEQ + l)*112 + k];
    }
    if (tid < 64) alphas[tid] = -1e30f;
    __syncthreads();

    int wid = tid >> 5, lane = tid & 31;
    const float isq = 0.09449111825230679f;  // 1/sqrt(112)
    for (int g = wid; 2*g < len; g += 4) {
        int l0 = 2*g, l1 = 2*g + 1;
        bool has1 = l1 < len;
        float d00 = 0.f, d01 = 0.f, d10 = 0.f, d11 = 0.f;
        int m0 = 2*lane, m1 = m0 + 1;
        if (lane < 25) {
            for (int k = 0; k < 112; k++) {
                float q0 = Qs[l0*112 + k];
                float2 kv = *(const float2*)&Kt[k*50 + m0];
                d00 = fmaf(q0, kv.x, d00);
                d01 = fmaf(q0, kv.y, d01);
                if (has1) {
                    float q1 = Qs[l1*112 + k];
                    d10 = fmaf(q1, kv.x, d10);
                    d11 = fmaf(q1, kv.y, d11);
                }
            }
        }
        float s0 = 0.f, s1 = 0.f;
        if (m0 < len && m0 != l0) s0 += isq / (1.f + __expf(-d00));
        if (m1 < len && m1 != l0) s0 += isq / (1.f + __expf(-d01));
        if (has1) {
            if (m0 < len && m0 != l1) s1 += isq / (1.f + __expf(-d10));
            if (m1 < len && m1 != l1) s1 += isq / (1.f + __expf(-d11));
        }
        #pragma unroll
        for (int o = 16; o; o >>= 1) {
            s0 += __shfl_down_sync(0xffffffffu, s0, o);
            s1 += __shfl_down_sync(0xffffffffu, s1, o);
        }
        if (lane == 0) {
            alphas[l0] = s0 / (float)len;
            if (has1) alphas[l1] = s1 / (float)len;
        }
    }
    __syncthreads();
    if (wid == 0) {
        float a1 = alphas[lane];
        float a2 = alphas[lane + 32];
        float mx = fmaxf(a1, a2);
        #pragma unroll
        for (int o = 16; o; o >>= 1) mx = fmaxf(mx, __shfl_xor_sync(0xffffffffu, mx, o));
        float e1 = __expf(a1 - mx), e2 = __expf(a2 - mx);
        float s = e1 + e2;
        #pragma unroll
        for (int o = 16; o; o >>= 1) s += __shfl_xor_sync(0xffffffffu, s, o);
        float inv = 1.f / s;
        betas[lane] = e1 * inv;
        betas[lane + 32] = e2 * inv;
    }
    __syncthreads();
    if (tid < 112) {
        float acc = 0.f;
        for (int l = 0; l < len; l++)
            acc = fmaf(betas[l], g_item[its[l]*112 + tid], acc);
        g_acc[b*112 + tid] = acc;
        xs[tid] = acc;
        g_t2[b*112 + tid] = 0.f;   // zero split-K targets for layer 0
        g_s1[b*112 + tid] = 0.f;
    }
    __syncthreads();
    if (tid < 112) {
        const float4* w4 = (const float4*)(W0 + tid*112);
        const float4* x4 = (const float4*)xs;
        float acc = 0.f;
        #pragma unroll 7
        for (int d = 0; d < 28; d++) {
            float4 w = w4[d], xv = x4[d];
            acc = fmaf(w.x, xv.x, acc);
            acc = fmaf(w.y, xv.y, acc);
            acc = fmaf(w.z, xv.z, acc);
            acc = fmaf(w.w, xv.w, acc);
        }
        g_t1[b*112 + tid] = acc;
    }
}

// ---------------- Linear out = in @ W^T; fused zeroing; normalize-accumulate ----------------
__global__ void k_lin(const float* __restrict__ in, const float* __restrict__ W,
                      float* __restrict__ out, float* __restrict__ z1,
                      float* __restrict__ z2, int donorm) {
    __shared__ __align__(16) float xs[112];
    __shared__ float red[4];
    int b = blockIdx.x, tid = threadIdx.x;
    float x = 0.f;
    if (tid < 112) {
        x = in[b*112 + tid];
        xs[tid] = x;
        z1[b*112 + tid] = 0.f;
        z2[b*112 + tid] = 0.f;
    }
    __syncthreads();
    if (donorm) {
        float ss = x*x;
        #pragma unroll
        for (int o = 16; o; o >>= 1) ss += __shfl_xor_sync(0xffffffffu, ss, o);
        if ((tid & 31) == 0) red[tid >> 5] = ss;
        __syncthreads();
        float tot = red[0] + red[1] + red[2] + red[3];
        float inv = 1.f / fmaxf(sqrtf(tot), 1e-12f);
        if (tid < 112) g_acc[b*112 + tid] += x * inv;
    }
    if (tid < 112) {
        const float4* w4 = (const float4*)(W + tid*112);
        const float4* x4 = (const float4*)xs;
        float acc = 0.f;
        #pragma unroll 7
        for (int d = 0; d < 28; d++) {
            float4 w = w4[d], xv = x4[d];
            acc = fmaf(w.x, xv.x, acc);
            acc = fmaf(w.y, xv.y, acc);
            acc = fmaf(w.z, xv.z, acc);
            acc = fmaf(w.w, xv.w, acc);
        }
        out[b*112 + tid] = acc;
    }
}

// ---------------- split-K GEMM: out += Amat[512,512] @ X[512,112] (atomic) ----------------
__global__ void k_gemm(const float* __restrict__ Amat, const float* __restrict__ X,
                       float* __restrict__ out) {
    __shared__ float As[64*17];
    __shared__ float Bs[16*112];
    int mt = blockIdx.x, ks = blockIdx.y;
    int row0 = mt*64, kbase = ks*64;
    int tid = threadIdx.x;
    int tx = tid & 15, ty = tid >> 4;
    float acc[4][7];
    #pragma unroll
    for (int i = 0; i < 4; i++)
        #pragma unroll
        for (int j = 0; j < 7; j++) acc[i][j] = 0.f;

    for (int kc = 0; kc < 64; kc += 16) {
        __syncthreads();
        for (int idx = tid; idx < 64*16; idx += 256) {
            int i = idx >> 4, kk = idx & 15;
            As[i*17 + kk] = Amat[(row0 + i)*512 + kbase + kc + kk];
        }
        for (int idx = tid; idx < 16*112; idx += 256) {
            int kk = idx / 112, e = idx - kk*112;
            Bs[kk*112 + e] = X[(kbase + kc + kk)*112 + e];
        }
        __syncthreads();
        #pragma unroll
        for (int kk = 0; kk < 16; kk++) {
            float a[4], bb[7];
            #pragma unroll
            for (int i = 0; i < 4; i++) a[i] = As[(ty + 16*i)*17 + kk];
            #pragma unroll
            for (int j = 0; j < 7; j++) bb[j] = Bs[kk*112 + tx + 16*j];
            #pragma unroll
            for (int i = 0; i < 4; i++)
                #pragma unroll
                for (int j = 0; j < 7; j++) acc[i][j] = fmaf(a[i], bb[j], acc[i][j]);
        }
    }
    #pragma unroll
    for (int i = 0; i < 4; i++)
        #pragma unroll
        for (int j = 0; j < 7; j++)
            atomicAdd(&out[(row0 + ty + 16*i)*112 + tx + 16*j], acc[i][j]);
}

// ---------------- final: acc2 = (g_acc + s2/||s2||) / 3 -> d_out; restore g_nvalid ----------------
__global__ void k_final(const float* __restrict__ cur, float* __restrict__ dout) {
    if (blockIdx.x == 0 && threadIdx.x == 0) g_nvalid = 0;
    int w = (blockIdx.x*blockDim.x + threadIdx.x) >> 5;
    if (w >= BATCH) return;
    int lane = threadIdx.x & 31;
    float4 v = make_float4(0.f, 0.f, 0.f, 0.f);
    float ss = 0.f;
    if (lane < 28) {
        v = ((const float4*)cur)[w*28 + lane];
        ss = v.x*v.x + v.y*v.y + v.z*v.z + v.w*v.w;
    }
    #pragma unroll
    for (int o = 16; o; o >>= 1) ss += __shfl_xor_sync(0xffffffffu, ss, o);
    float inv = 1.f / fmaxf(sqrtf(ss), 1e-12f);
    if (lane < 28) {
        float4 a = ((const float4*)g_acc)[w*28 + lane];
        const float third = 1.f/3.f;
        a.x = fmaf(v.x, inv, a.x) * third;
        a.y = fmaf(v.y, inv, a.y) * third;
        a.z = fmaf(v.z, inv, a.z) * third;
        a.w = fmaf(v.w, inv, a.w) * third;
        ((float4*)dout)[w*28 + lane] = a;
    }
}

// ---------------- host launcher ----------------
extern "C" void kernel_launch(void* const* d_in, const int* in_sizes, int n_in,
                              void* d_out, int out_size) {
    (void)in_sizes; (void)n_in; (void)out_size;
    const float* emb      = (const float*)d_in[0];
    const float* adj_vals = (const float*)d_in[1];
    const float* Wq       = (const float*)d_in[2];
    const float* Wk       = (const float*)d_in[3];
    const float* Wsess    = (const float*)d_in[4];
    const float* D        = (const float*)d_in[5];
    const float* A        = (const float*)d_in[6];
    const int*   rows     = (const int*)d_in[7];
    const int*   cols     = (const int*)d_in[8];
    const int*   sitem    = (const int*)d_in[9];
    const int*   slen     = (const int*)d_in[10];
    float*       out      = (float*)d_out;

    float *p_item, *p_t1, *p_t2, *p_s1, *p_s2;
    cudaGetSymbolAddress((void**)&p_item, g_item);
    cudaGetSymbolAddress((void**)&p_t1, g_t1);
    cudaGetSymbolAddress((void**)&p_t2, g_t2);
    cudaGetSymbolAddress((void**)&p_s1, g_s1);
    cudaGetSymbolAddress((void**)&p_s2, g_s2);

    // CSR build; fp16 conversion rides on scan1's idle SMs
    k_hist<<<(NNZ + 255)/256, 256>>>(rows, sitem, slen);
    k_scan1<<<NBLK + CONVBLK, 1024>>>((const float4*)emb);
    k_scatter<<<NNZ/512, 512>>>(rows, cols, adj_vals);

    // HyperConv layers: 128-thread blocks (4 rows), fp16-only tables
    k_spmm_h<<<(N_NODE + 3)/4, 128>>>();
    k_spmm2<<<(N_NODE + 3)/4, 128>>>((float4*)p_item);

    // Q/K + attention pooling (layer-0 linear fused into attn)
    k_qk<<<NR/64, 256>>>(Wq, Wk, sitem);
    k_attn<<<BATCH, 128>>>(slen, sitem, Wsess);

    // SessConv layer 0 (linear already done in attn)
    k_gemm<<<dim3(8, 8), 256>>>(A, p_t1, p_t2);
    k_gemm<<<dim3(8, 8), 256>>>(D, p_t2, p_s1);

    // SessConv layer 1 (fused normalize(s1)->acc)
    k_lin<<<BATCH, 128>>>(p_s1, Wsess + 112*112, p_t1, p_t2, p_s2, 1);
    k_gemm<<<dim3(8, 8), 256>>>(A, p_t1, p_t2);
    k_gemm<<<dim3(8, 8), 256>>>(D, p_t2, p_s2);

    k_final<<<(BATCH*32 + 255)/256, 256>>>(p_s2, out);
}